// round 3
// baseline (speedup 1.0000x reference)
#include <cuda_runtime.h>
#include <cuda_bf16.h>

#define KNN 32
#define NPB 128
typedef unsigned long long u64;
#define SENT 0xFFFFFFFFFFFFFFFFULL

// One block per molecule (128 contiguous atoms). Thread t handles node base+t:
// computes d2 to all 128 candidates from shared memory, keeps the 32 smallest
// in-radius (d2<=25) keys sorted ascending in registers via a bubble-insert.
// Key = (d2_bits << 32) | local_j  -> ordering == (d2 asc, index asc), which
// matches jax.lax.top_k(-masked) tie-breaking exactly.
//
// d2 arithmetic replicates the reference's (XLA, contraction-on) rounding:
//   sq   = fma(z,z, fma(y,y, x*x))       (mul fused into the reduce)
//   dot  = fma(z,z', fma(y,y', x*x'))    (K=3 fma accumulation, acc0 = rn(x*x'))
//   d2   = max((sq_i + sq_j) - 2*dot, 0) (2*dot exact, sub rounded)
__global__ __launch_bounds__(NPB) void radius_graph_kernel(
    const float* __restrict__ pos, const int* __restrict__ batch,
    float* __restrict__ out, int N) {
  __shared__ float sx[NPB], sy[NPB], sz[NPB], ssq[NPB];
  __shared__ int sb[NPB];

  const int tid  = threadIdx.x;
  const int base = blockIdx.x * NPB;
  const int n    = base + tid;

  const float x = pos[3 * n + 0];
  const float y = pos[3 * n + 1];
  const float z = pos[3 * n + 2];
  const float sq = __fmaf_rn(z, z, __fmaf_rn(y, y, __fmul_rn(x, x)));
  sx[tid] = x; sy[tid] = y; sz[tid] = z; ssq[tid] = sq;
  sb[tid] = batch[n];
  __syncthreads();

  const int bme = sb[tid];

  u64 keys[KNN];
#pragma unroll
  for (int k = 0; k < KNN; k++) keys[k] = SENT;

  for (int j = 0; j < NPB; j++) {
    if (sb[j] != bme) continue;
    // FMA-chain dot product, matching XLA/BLAS accumulation order.
    const float dot =
        __fmaf_rn(z, sz[j], __fmaf_rn(y, sy[j], __fmul_rn(x, sx[j])));
    float d2 = __fsub_rn(__fadd_rn(sq, ssq[j]), __fmul_rn(2.0f, dot));
    d2 = fmaxf(d2, 0.0f);
    if (d2 <= 25.0f) {
      u64 c = ((u64)__float_as_uint(d2) << 32) | (unsigned)j;
      if (c < keys[KNN - 1]) {
        // Bubble-insert: keeps keys[] sorted ascending, evicts the max.
#pragma unroll
        for (int k = 0; k < KNN; k++) {
          const u64 a = keys[k];
          const u64 lo = (a < c) ? a : c;
          const u64 hi = (a < c) ? c : a;
          keys[k] = lo;
          c = hi;
        }
      }
    }
  }

  // Output layout (float32): src[NK] | dst[NK] | weight[NK] | vec[NK*3]
  const long long NK = (long long)N * KNN;
  float* __restrict__ o_src = out;
  float* __restrict__ o_dst = out + NK;
  float* __restrict__ o_w   = out + 2 * NK;
  float* __restrict__ o_v   = out + 3 * NK;

  const int e0 = n * KNN;
  const float fn = (float)n;

#pragma unroll
  for (int k = 0; k < KNN; k++) {
    const u64 key = keys[k];
    const int j = (key == SENT) ? tid : (int)(unsigned)(key & 0xFFFFFFFFu);
    const int col = base + j;
    const float vx = x - sx[j];
    const float vy = y - sy[j];
    const float vz = z - sz[j];
    const float ssv = __fadd_rn(
        __fadd_rn(__fmul_rn(vx, vx), __fmul_rn(vy, vy)), __fmul_rn(vz, vz));
    const float w = (j == tid) ? 0.0f : __fsqrt_rn(ssv);

    o_src[e0 + k] = fn;
    o_dst[e0 + k] = (float)col;
    o_w[e0 + k]   = w;
    o_v[3 * (e0 + k) + 0] = vx;
    o_v[3 * (e0 + k) + 1] = vy;
    o_v[3 * (e0 + k) + 2] = vz;
  }
}

extern "C" void kernel_launch(void* const* d_in, const int* in_sizes, int n_in,
                              void* d_out, int out_size) {
  const float* pos  = (const float*)d_in[0];
  const int* batch  = (const int*)d_in[1];
  const int N = in_sizes[0] / 3;       // pos is [N,3]
  const int nblocks = N / NPB;         // 96 molecules of 128 atoms
  radius_graph_kernel<<<nblocks, NPB>>>(pos, batch, (float*)d_out, N);
}

// round 4
// speedup vs baseline: 3.1486x; 3.1486x over previous
#include <cuda_runtime.h>
#include <cuda_bf16.h>

#define KNN 32
#define NPB 128            // atoms per molecule (contiguous, 128-aligned)
#define NODES_PER_CTA 4    // 4 warps per CTA, one node per warp
typedef unsigned long long u64;
#define SENT 0xFFFFFFFFFFFFFFFFULL

__device__ __forceinline__ u64 shflx(u64 v, int m) {
  return __shfl_xor_sync(0xFFFFFFFFu, v, m);
}

// Merge two ascending 32-element warp sequences (one element per lane),
// return the 32 smallest, sorted ascending by lane.
// min(A, reverse(B)) = half-cleaner of the 64-element bitonic concat ->
// lower half is bitonic and holds the 32 smallest; 5-stage bitonic merge sorts it.
__device__ __forceinline__ u64 merge_keep_low(u64 a, u64 b, int lane) {
  u64 brev = __shfl_sync(0xFFFFFFFFu, b, 31 - lane);
  u64 t = (a < brev) ? a : brev;
#pragma unroll
  for (int j = 16; j > 0; j >>= 1) {
    const u64 o = shflx(t, j);
    const u64 mn = (t < o) ? t : o;
    const u64 mx = (t < o) ? o : t;
    t = ((lane & j) == 0) ? mn : mx;
  }
  return t;
}

// Warp-per-node radius graph. Key = (d2_bits << 32) | j reproduces
// jax.lax.top_k(-masked) ordering exactly: (d2 asc, index asc), SENT = +inf.
// d2 arithmetic replicates the reference's (XLA, contraction-on) rounding:
//   sq  = fma(z,z, fma(y,y, x*x))
//   dot = fma(z,z', fma(y,y', x*x'))
//   d2  = max((sq_i + sq_j) - 2*dot, 0)
__global__ __launch_bounds__(NPB) void radius_graph_kernel(
    const float* __restrict__ pos, const int* __restrict__ batch,
    float* __restrict__ out, int N) {
  __shared__ float sx[NPB], sy[NPB], sz[NPB], ssq[NPB];
  __shared__ int sb[NPB];

  const int tid  = threadIdx.x;
  const int lane = tid & 31;
  const int wid  = tid >> 5;
  const int n    = blockIdx.x * NODES_PER_CTA + wid;
  const int molbase = n & ~(NPB - 1);

  // Stage the molecule's 128 atoms into smem (one atom per thread).
  {
    const int a = tid;
    const float ax = pos[3 * (molbase + a) + 0];
    const float ay = pos[3 * (molbase + a) + 1];
    const float az = pos[3 * (molbase + a) + 2];
    sx[a] = ax; sy[a] = ay; sz[a] = az;
    ssq[a] = __fmaf_rn(az, az, __fmaf_rn(ay, ay, __fmul_rn(ax, ax)));
    sb[a]  = batch[molbase + a];
  }
  __syncthreads();

  const int self = n & (NPB - 1);
  const float x = sx[self], y = sy[self], z = sz[self];
  const float sq = ssq[self];
  const int bme = sb[self];

  // Candidate keys: column m holds j = m*32 + lane across the warp.
  u64 r[4];
#pragma unroll
  for (int m = 0; m < 4; m++) {
    const int j = m * 32 + lane;
    const float dot =
        __fmaf_rn(z, sz[j], __fmaf_rn(y, sy[j], __fmul_rn(x, sx[j])));
    float d2 = __fsub_rn(__fadd_rn(sq, ssq[j]), __fmul_rn(2.0f, dot));
    d2 = fmaxf(d2, 0.0f);
    const bool ok = (sb[j] == bme) && (d2 <= 25.0f);
    r[m] = ok ? (((u64)__float_as_uint(d2) << 32) | (unsigned)j) : SENT;
  }

  // Bitonic-sort each of the 4 columns ascending by lane (4-way ILP).
#pragma unroll
  for (int k = 2; k <= 32; k <<= 1) {
#pragma unroll
    for (int j = k >> 1; j > 0; j >>= 1) {
      const bool keepMin = (((lane & j) == 0) == ((lane & k) == 0));
#pragma unroll
      for (int m = 0; m < 4; m++) {
        const u64 o = shflx(r[m], j);
        const u64 mn = (r[m] < o) ? r[m] : o;
        const u64 mx = (r[m] < o) ? o : r[m];
        r[m] = keepMin ? mn : mx;
      }
    }
  }

  // Tournament of keep-low merges -> lane l holds final sorted slot l.
  const u64 t01 = merge_keep_low(r[0], r[1], lane);
  const u64 t23 = merge_keep_low(r[2], r[3], lane);
  const u64 key = merge_keep_low(t01, t23, lane);

  // Emit slot `lane` of node n.
  const int j = (key == SENT) ? self : (int)(unsigned)key;
  const float vx = x - sx[j];
  const float vy = y - sy[j];
  const float vz = z - sz[j];
  const float ssv =
      __fmaf_rn(vz, vz, __fmaf_rn(vy, vy, __fmul_rn(vx, vx)));
  const float w = (j == self) ? 0.0f : __fsqrt_rn(ssv);

  const long long NK = (long long)N * KNN;
  const int e = n * KNN + lane;
  out[e]          = (float)n;
  out[NK + e]     = (float)(molbase + j);
  out[2 * NK + e] = w;
  float* __restrict__ ov = out + 3 * NK + 3LL * e;
  ov[0] = vx; ov[1] = vy; ov[2] = vz;
}

extern "C" void kernel_launch(void* const* d_in, const int* in_sizes, int n_in,
                              void* d_out, int out_size) {
  const float* pos  = (const float*)d_in[0];
  const int* batch  = (const int*)d_in[1];
  const int N = in_sizes[0] / 3;            // pos is [N,3]
  const int nblocks = N / NODES_PER_CTA;    // one warp per node
  radius_graph_kernel<<<nblocks, NPB>>>(pos, batch, (float*)d_out, N);
}

// round 5
// speedup vs baseline: 3.1994x; 1.0161x over previous
#include <cuda_runtime.h>
#include <cuda_bf16.h>

#define KNN 32
#define NPB 128            // atoms per molecule (contiguous, 128-aligned)
#define NPW 2              // nodes per warp (ILP)
#define WARPS_PER_CTA 4
#define NODES_PER_CTA (NPW * WARPS_PER_CTA)  // 8
typedef unsigned long long u64;
#define SENT 0xFFFFFFFFFFFFFFFFULL

__device__ __forceinline__ u64 shflx(u64 v, int m) {
  return __shfl_xor_sync(0xFFFFFFFFu, v, m);
}

// Merge two ascending 32-element warp sequences (one element per lane),
// return the 32 smallest, sorted ascending by lane.
__device__ __forceinline__ u64 merge_keep_low(u64 a, u64 b, int lane) {
  u64 brev = __shfl_sync(0xFFFFFFFFu, b, 31 - lane);
  u64 t = (a < brev) ? a : brev;
#pragma unroll
  for (int j = 16; j > 0; j >>= 1) {
    const u64 o = shflx(t, j);
    const u64 mn = (t < o) ? t : o;
    const u64 mx = (t < o) ? o : t;
    t = ((lane & j) == 0) ? mn : mx;
  }
  return t;
}

// Warp handles NPW nodes (ILP across independent bitonic streams).
// Key = (d2_bits << 32) | j reproduces jax.lax.top_k(-masked) ordering exactly:
// (d2 asc, index asc); SENT = +inf. Keys are unique (idx differs) -> exact.
// d2 arithmetic replicates the reference's (XLA, contraction-on) rounding:
//   sq  = fma(z,z, fma(y,y, x*x))
//   dot = fma(z,z', fma(y,y', x*x'))
//   d2  = max((sq_i + sq_j) - 2*dot, 0)
__global__ __launch_bounds__(NPB) void radius_graph_kernel(
    const float* __restrict__ pos, const int* __restrict__ batch,
    float* __restrict__ out, int N) {
  __shared__ float sx[NPB], sy[NPB], sz[NPB], ssq[NPB];
  __shared__ int sb[NPB];

  const int tid  = threadIdx.x;
  const int lane = tid & 31;
  const int wid  = tid >> 5;
  const int nbase = blockIdx.x * NODES_PER_CTA;
  const int molbase = nbase & ~(NPB - 1);

  // Stage the molecule's 128 atoms into smem (one atom per thread).
  {
    const float ax = pos[3 * (molbase + tid) + 0];
    const float ay = pos[3 * (molbase + tid) + 1];
    const float az = pos[3 * (molbase + tid) + 2];
    sx[tid] = ax; sy[tid] = ay; sz[tid] = az;
    ssq[tid] = __fmaf_rn(az, az, __fmaf_rn(ay, ay, __fmul_rn(ax, ax)));
    sb[tid]  = batch[molbase + tid];
  }
  __syncthreads();

  const int n0 = nbase + wid * NPW;  // first node of this warp

  float X[NPW], Y[NPW], Z[NPW], SQ[NPW];
  int BM[NPW], SELF[NPW];
#pragma unroll
  for (int p = 0; p < NPW; p++) {
    const int self = (n0 + p) & (NPB - 1);
    SELF[p] = self;
    X[p] = sx[self]; Y[p] = sy[self]; Z[p] = sz[self];
    SQ[p] = ssq[self]; BM[p] = sb[self];
  }

  // Candidate keys: column m holds j = m*32 + lane; shared loads amortized
  // across the NPW nodes.
  u64 r[NPW][4];
#pragma unroll
  for (int m = 0; m < 4; m++) {
    const int j = m * 32 + lane;
    const float cx = sx[j], cy = sy[j], cz = sz[j];
    const float csq = ssq[j];
    const int cb = sb[j];
#pragma unroll
    for (int p = 0; p < NPW; p++) {
      const float dot =
          __fmaf_rn(Z[p], cz, __fmaf_rn(Y[p], cy, __fmul_rn(X[p], cx)));
      float d2 = __fsub_rn(__fadd_rn(SQ[p], csq), __fmul_rn(2.0f, dot));
      d2 = fmaxf(d2, 0.0f);
      const bool ok = (cb == BM[p]) && (d2 <= 25.0f);
      r[p][m] = ok ? (((u64)__float_as_uint(d2) << 32) | (unsigned)j) : SENT;
    }
  }

  // Bitonic-sort each column ascending by lane (NPW*4 = 8-way ILP).
#pragma unroll
  for (int k = 2; k <= 32; k <<= 1) {
#pragma unroll
    for (int j = k >> 1; j > 0; j >>= 1) {
      const bool keepMin = (((lane & j) == 0) == ((lane & k) == 0));
#pragma unroll
      for (int p = 0; p < NPW; p++) {
#pragma unroll
        for (int m = 0; m < 4; m++) {
          const u64 o = shflx(r[p][m], j);
          const u64 mn = (r[p][m] < o) ? r[p][m] : o;
          const u64 mx = (r[p][m] < o) ? o : r[p][m];
          r[p][m] = keepMin ? mn : mx;
        }
      }
    }
  }

  // Tournament of keep-low merges per node (independent across p).
  u64 key[NPW];
#pragma unroll
  for (int p = 0; p < NPW; p++) {
    const u64 t01 = merge_keep_low(r[p][0], r[p][1], lane);
    const u64 t23 = merge_keep_low(r[p][2], r[p][3], lane);
    key[p] = merge_keep_low(t01, t23, lane);
  }

  // Emit slot `lane` of each node.
  const long long NK = (long long)N * KNN;
#pragma unroll
  for (int p = 0; p < NPW; p++) {
    const int n = n0 + p;
    const int j = (key[p] == SENT) ? SELF[p] : (int)(unsigned)key[p];
    const float vx = X[p] - sx[j];
    const float vy = Y[p] - sy[j];
    const float vz = Z[p] - sz[j];
    const float ssv =
        __fmaf_rn(vz, vz, __fmaf_rn(vy, vy, __fmul_rn(vx, vx)));
    const float w = (j == SELF[p]) ? 0.0f : __fsqrt_rn(ssv);

    const int e = n * KNN + lane;
    out[e]          = (float)n;
    out[NK + e]     = (float)(molbase + j);
    out[2 * NK + e] = w;
    float* __restrict__ ov = out + 3 * NK + 3LL * e;
    ov[0] = vx; ov[1] = vy; ov[2] = vz;
  }
}

extern "C" void kernel_launch(void* const* d_in, const int* in_sizes, int n_in,
                              void* d_out, int out_size) {
  const float* pos  = (const float*)d_in[0];
  const int* batch  = (const int*)d_in[1];
  const int N = in_sizes[0] / 3;            // pos is [N,3]
  const int nblocks = N / NODES_PER_CTA;    // 8 nodes per CTA, 2 per warp
  radius_graph_kernel<<<nblocks, NPB>>>(pos, batch, (float*)d_out, N);
}